// round 14
// baseline (speedup 1.0000x reference)
#include <cuda_runtime.h>
#include <cuda_fp16.h>
#include <math.h>
#include <stdint.h>

// Problem constants
#define B_    128
#define F_    1024
#define D_IN  128
#define H1_   512
#define H2_   512
#define E_    256
#define H_    256
#define NSH   5
#define MROWS (B_ * F_)   // 131072

// ---------------- scratch (device globals; no allocation allowed) ----------
__device__ __half g_h1[(size_t)MROWS * H1_];
__device__ __half g_h2[(size_t)MROWS * H2_];
__device__ __half g_w1[H1_ * D_IN];
__device__ __half g_w2[H2_ * H1_];
__device__ __half g_w3[E_ * H2_];
__device__ __half g_wih[4 * H_ * E_];
__device__ __half g_whh[4 * H_ * H_];
__device__ __half g_embh[(size_t)MROWS * E_];   // 67 MB, fp16 emb
__device__ float  g_att[B_ * E_];
__device__ float  g_qt[B_ * H_];
__device__ float  g_ct[B_ * H_];
__device__ float  g_gates[B_ * 4 * H_];

// ===================== low-level helpers ===================================
__device__ __forceinline__ uint32_t smem_u32(const void* p) {
    uint32_t a;
    asm("{ .reg .u64 t; cvta.to.shared.u64 t, %1; cvt.u32.u64 %0, t; }"
        : "=r"(a) : "l"(p));
    return a;
}

__device__ __forceinline__ void cp_async16(uint32_t dst, const void* src) {
    asm volatile("cp.async.cg.shared.global [%0], [%1], 16;\n"
                 :: "r"(dst), "l"(src));
}
#define CP_COMMIT() asm volatile("cp.async.commit_group;\n" ::: "memory")
#define CP_WAIT1()  asm volatile("cp.async.wait_group 1;\n" ::: "memory")
#define CP_WAIT0()  asm volatile("cp.async.wait_group 0;\n" ::: "memory")

__device__ __forceinline__ void ldsm4(uint32_t* r, uint32_t addr) {
    asm volatile("ldmatrix.sync.aligned.m8n8.x4.shared.b16 {%0,%1,%2,%3}, [%4];\n"
                 : "=r"(r[0]), "=r"(r[1]), "=r"(r[2]), "=r"(r[3]) : "r"(addr));
}

// fp16 HMMA m16n8k16, fp32 accumulate
__device__ __forceinline__ void mma_f16(float* d, const uint32_t* a, const uint32_t* b) {
    asm volatile(
        "mma.sync.aligned.m16n8k16.row.col.f32.f16.f16.f32 "
        "{%0,%1,%2,%3}, {%4,%5,%6,%7}, {%8,%9}, {%0,%1,%2,%3};\n"
        : "+f"(d[0]), "+f"(d[1]), "+f"(d[2]), "+f"(d[3])
        : "r"(a[0]), "r"(a[1]), "r"(a[2]), "r"(a[3]), "r"(b[0]), "r"(b[1]));
}

__device__ __forceinline__ uint32_t pack_h2(float a, float b) {
    __half2 t = __floats2half2_rn(a, b);
    return reinterpret_cast<uint32_t&>(t);
}

// =================== fp16 HMMA GEMM: C = act(A @ W^T + bias) ================
// CTA tile 128x256, 256 threads, warp grid 2m x 4n, warp tile 64x64.
// BK=128 (256B rows, XOR swizzle), 2-stage cp.async, 1 CTA/SM.
// CONV_A: A is fp32 in global; staged via LDG->cvt->STS (layer 1, K=128).
static constexpr int TA      = 128 * 256;          // 32768 B  A tile
static constexpr int TW      = 256 * 256;          // 65536 B  W tile
static constexpr int OFF_A   = 0;
static constexpr int OFF_W   = TA;
static constexpr int STAGE_B = TA + TW;            // 98304 B
static constexpr int GEMM_SM = 2 * STAGE_B;        // 196608 B

template <int ACT, int OUT_HALF, int CONV_A>
__global__ __launch_bounds__(256, 1) void gemm_f16_kernel(
    int M, int N, int K,
    const __half* __restrict__ A, const float* __restrict__ Afp,
    const __half* __restrict__ W,
    const float* __restrict__ bias,
    float* __restrict__ C, __half* __restrict__ Ch)
{
    extern __shared__ char smem[];
    const uint32_t sbase = smem_u32(smem);
    const int tid  = threadIdx.x;
    const int lane = tid & 31;
    const int wid  = tid >> 5;            // 0..7
    const int m0 = blockIdx.y * 128;
    const int n0 = blockIdx.x * 256;
    const int wm = (wid & 1) * 64;        // warp m-offset
    const int wn = (wid >> 1) * 64;       // warp n-offset (0..192)

    float acc[4][8][4];
#pragma unroll
    for (int i = 0; i < 4; i++)
#pragma unroll
        for (int j = 0; j < 8; j++)
#pragma unroll
            for (int k = 0; k < 4; k++) acc[i][j][k] = 0.f;

    // ---- ldmatrix row bases ----
    uint32_t aRow[4], aX[4];
#pragma unroll
    for (int am = 0; am < 4; am++) {
        const int r = wm + am * 16 + (lane & 15);
        aRow[am] = (uint32_t)(r * 256);
        aX[am]   = (uint32_t)(r & 7);
    }
    uint32_t bRow[4], bX[4];
#pragma unroll
    for (int pb = 0; pb < 4; pb++) {
        const int r = wn + pb * 16 + (lane & 7) + ((lane >> 1) & 8);
        bRow[pb] = (uint32_t)(r * 256);
        bX[pb]   = (uint32_t)(r & 7);
    }
    const uint32_t ac0 = (uint32_t)(lane >> 4);
    const uint32_t bc0 = (uint32_t)((lane >> 3) & 1);

    const int NC = K >> 7;   // chunks of 128 fp16

    auto prefetch = [&](int cc, int st) {
        const uint32_t so = sbase + (uint32_t)(st * STAGE_B);
        const int kk = cc * 128;
#pragma unroll
        for (int i = 0; i < 16; i++) {
            const int id  = i * 256 + tid;       // 0..4095
            const int row = id >> 4;
            const int c16 = id & 15;
            cp_async16(so + OFF_W + row * 256 + (((uint32_t)(c16 ^ (row & 7))) << 4),
                       W + (size_t)(n0 + row) * K + kk + c16 * 8);
        }
        if (CONV_A) {
#pragma unroll
            for (int i = 0; i < 8; i++) {
                const int id  = i * 256 + tid;   // 0..2047
                const int row = id >> 4;
                const int c16 = id & 15;
                const float* src = Afp + (size_t)(m0 + row) * K + kk + c16 * 8;
                const float4 u = *reinterpret_cast<const float4*>(src);
                const float4 v = *reinterpret_cast<const float4*>(src + 4);
                uint4 pk;
                pk.x = pack_h2(u.x, u.y); pk.y = pack_h2(u.z, u.w);
                pk.z = pack_h2(v.x, v.y); pk.w = pack_h2(v.z, v.w);
                *reinterpret_cast<uint4*>(
                    smem + (so - sbase) + OFF_A + row * 256
                    + (((uint32_t)(c16 ^ (row & 7))) << 4)) = pk;
            }
        } else {
#pragma unroll
            for (int i = 0; i < 8; i++) {
                const int id  = i * 256 + tid;
                const int row = id >> 4;
                const int c16 = id & 15;
                cp_async16(so + OFF_A + row * 256 + (((uint32_t)(c16 ^ (row & 7))) << 4),
                           A + (size_t)(m0 + row) * K + kk + c16 * 8);
            }
        }
        CP_COMMIT();
    };

    prefetch(0, 0);

    for (int cc = 0; cc < NC; cc++) {
        if (cc + 1 < NC) { prefetch(cc + 1, (cc + 1) & 1); CP_WAIT1(); }
        else             { CP_WAIT0(); }
        __syncthreads();

        const uint32_t st = sbase + (cc & 1) * STAGE_B;
#pragma unroll
        for (int s = 0; s < 8; s++) {
            const uint32_t ac = ac0 + 2 * s;
            const uint32_t bc = bc0 + 2 * s;

            uint32_t ah[4][4];
#pragma unroll
            for (int am = 0; am < 4; am++)
                ldsm4(ah[am], st + OFF_A + aRow[am] + ((ac ^ aX[am]) << 4));
            uint32_t bv[8][2];
#pragma unroll
            for (int pb = 0; pb < 4; pb++) {
                uint32_t r[4];
                ldsm4(r, st + OFF_W + bRow[pb] + ((bc ^ bX[pb]) << 4));
                bv[2 * pb][0] = r[0]; bv[2 * pb][1] = r[1];
                bv[2 * pb + 1][0] = r[2]; bv[2 * pb + 1][1] = r[3];
            }
#pragma unroll
            for (int am = 0; am < 4; am++)
#pragma unroll
                for (int an = 0; an < 8; an++) mma_f16(acc[am][an], ah[am], bv[an]);
        }
        __syncthreads();
    }

    // epilogue: bias (+ReLU), store fp32 or fp16
#pragma unroll
    for (int am = 0; am < 4; am++) {
        const int r0 = m0 + wm + am * 16 + (lane >> 2);
        const int r1 = r0 + 8;
#pragma unroll
        for (int an = 0; an < 8; an++) {
            const int col = n0 + wn + an * 8 + ((lane & 3) << 1);
            const float bz0 = __ldg(&bias[col]);
            const float bz1 = __ldg(&bias[col + 1]);
            float v00 = acc[am][an][0] + bz0;
            float v01 = acc[am][an][1] + bz1;
            float v10 = acc[am][an][2] + bz0;
            float v11 = acc[am][an][3] + bz1;
            if (ACT) {
                v00 = fmaxf(v00, 0.f); v01 = fmaxf(v01, 0.f);
                v10 = fmaxf(v10, 0.f); v11 = fmaxf(v11, 0.f);
            }
            if (OUT_HALF) {
                *reinterpret_cast<uint32_t*>(&Ch[(size_t)r0 * N + col]) = pack_h2(v00, v01);
                *reinterpret_cast<uint32_t*>(&Ch[(size_t)r1 * N + col]) = pack_h2(v10, v11);
            } else {
                *reinterpret_cast<float2*>(&C[(size_t)r0 * N + col]) = make_float2(v00, v01);
                *reinterpret_cast<float2*>(&C[(size_t)r1 * N + col]) = make_float2(v10, v11);
            }
        }
    }
}

// ---------------- fp32 -> fp16 converts (all weights, one launch) ----------
__device__ __forceinline__ void conv4(const float* src, __half* dst, int i) {
    float4 v = *reinterpret_cast<const float4*>(src + i);
    *reinterpret_cast<uint2*>(&dst[i]) =
        make_uint2(pack_h2(v.x, v.y), pack_h2(v.z, v.w));
}

__global__ __launch_bounds__(256) void conv_weights_kernel(
    const float* __restrict__ W1, __half* __restrict__ w1,
    const float* __restrict__ W2, __half* __restrict__ w2,
    const float* __restrict__ W3, __half* __restrict__ w3,
    const float* __restrict__ Wih, __half* __restrict__ wih,
    const float* __restrict__ Whh, __half* __restrict__ whh)
{
    const int N1 = H1_ * D_IN, N2 = H2_ * H1_, N3 = E_ * H2_;
    const int N4 = 4 * H_ * E_, N5 = 4 * H_ * H_;
    int i = (blockIdx.x * 256 + threadIdx.x) * 4;
    if (i < N1)                      conv4(W1, w1, i);
    else if (i < N1 + N2)            conv4(W2, w2, i - N1);
    else if (i < N1 + N2 + N3)       conv4(W3, w3, i - N1 - N2);
    else if (i < N1 + N2 + N3 + N4)  conv4(Wih, wih, i - N1 - N2 - N3);
    else if (i < N1 + N2 + N3 + N4 + N5) conv4(Whh, whh, i - N1 - N2 - N3 - N4);
}

// ---------------- LSTM state update from gates (shared helper) -------------
__device__ __forceinline__ float lstm_update(const float* g, int h, float cin, float* cout) {
    const float gi = 1.f / (1.f + expf(-g[h]));
    const float gf = 1.f / (1.f + expf(-g[H_ + h]));
    const float gg = tanhf(g[2 * H_ + h]);
    const float go = 1.f / (1.f + expf(-g[3 * H_ + h]));
    const float c = gf * cin + gi * gg;
    *cout = c;
    return go * tanhf(c);
}

// ============ att_k: apply prev LSTM update, then online-softmax attention =
__global__ __launch_bounds__(1024) void att_kernel(
    const __half* __restrict__ emb, const int* __restrict__ length,
    const float* __restrict__ gates, float* __restrict__ qt_g,
    float* __restrict__ ct_g, float* __restrict__ att_g, int first)
{
    const int b    = blockIdx.x;
    const int tid  = threadIdx.x;
    const int warp = tid >> 5, lane = tid & 31;

    __shared__ __align__(16) float s_q[H_];
    __shared__ __align__(16) float s_part[32][E_ + 4];
    __shared__ float s_m[32], s_l[32], s_fac[32];
    __shared__ float s_invL;

    if (tid < H_) {
        if (first) {
            s_q[tid] = 0.f;
            qt_g[b * H_ + tid] = 0.f;
            ct_g[b * H_ + tid] = 0.f;
        } else {
            float c;
            const float h = lstm_update(gates + b * 4 * H_, tid,
                                        ct_g[b * H_ + tid], &c);
            s_q[tid] = h;
            qt_g[b * H_ + tid] = h;
            ct_g[b * H_ + tid] = c;
        }
    }
    __syncthreads();

    const int len = length[b];
    const __half* eb = emb + (size_t)b * F_ * E_;
    const float4* q4 = reinterpret_cast<const float4*>(s_q);

    float m = -INFINITY, l = 0.f;
    float acc[8];
#pragma unroll
    for (int j = 0; j < 8; j++) acc[j] = 0.f;
    const float4 qa = q4[lane * 2], qb = q4[lane * 2 + 1];
    const float qv[8] = { qa.x, qa.y, qa.z, qa.w, qb.x, qb.y, qb.z, qb.w };
    const int fb = warp * 32;
#pragma unroll 2
    for (int ff = 0; ff < 32; ff += 2) {
        const int f0 = fb + ff, f1 = f0 + 1;
        const uint4 h0 = reinterpret_cast<const uint4*>(eb + (size_t)f0 * E_)[lane];
        const uint4 h1 = reinterpret_cast<const uint4*>(eb + (size_t)f1 * E_)[lane];
        const __half2* p0 = reinterpret_cast<const __half2*>(&h0);
        const __half2* p1 = reinterpret_cast<const __half2*>(&h1);
        float v0[8], v1[8];
#pragma unroll
        for (int k = 0; k < 4; k++) {
            const float2 a2 = __half22float2(p0[k]);
            const float2 b2 = __half22float2(p1[k]);
            v0[2 * k] = a2.x; v0[2 * k + 1] = a2.y;
            v1[2 * k] = b2.x; v1[2 * k + 1] = b2.y;
        }
        float d0 = v0[0] * qv[0], d1 = v1[0] * qv[0];
#pragma unroll
        for (int j = 1; j < 8; j++) {
            d0 = fmaf(v0[j], qv[j], d0);
            d1 = fmaf(v1[j], qv[j], d1);
        }
#pragma unroll
        for (int o = 16; o; o >>= 1) {
            d0 += __shfl_xor_sync(0xffffffffu, d0, o);
            d1 += __shfl_xor_sync(0xffffffffu, d1, o);
        }
        if (f0 < len) {
            const float mn = fmaxf(m, d0);
            const float sc = expf(m - mn);
            const float p  = expf(d0 - mn);
            l = l * sc + p;
#pragma unroll
            for (int j = 0; j < 8; j++) acc[j] = fmaf(acc[j], sc, p * v0[j]);
            m = mn;
        }
        if (f1 < len) {
            const float mn = fmaxf(m, d1);
            const float sc = expf(m - mn);
            const float p  = expf(d1 - mn);
            l = l * sc + p;
#pragma unroll
            for (int j = 0; j < 8; j++) acc[j] = fmaf(acc[j], sc, p * v1[j]);
            m = mn;
        }
    }
    {
        float4* sp = reinterpret_cast<float4*>(s_part[warp]);
        sp[lane * 2]     = make_float4(acc[0], acc[1], acc[2], acc[3]);
        sp[lane * 2 + 1] = make_float4(acc[4], acc[5], acc[6], acc[7]);
        if (lane == 0) { s_m[warp] = m; s_l[warp] = l; }
    }
    __syncthreads();

    if (tid < 32) {
        const float mw = s_m[tid];
        float M = mw;
#pragma unroll
        for (int o = 16; o; o >>= 1) M = fmaxf(M, __shfl_xor_sync(0xffffffffu, M, o));
        const float fac = expf(mw - M);
        s_fac[tid] = fac;
        float L = s_l[tid] * fac;
#pragma unroll
        for (int o = 16; o; o >>= 1) L += __shfl_xor_sync(0xffffffffu, L, o);
        if (tid == 0) s_invL = 1.f / L;
    }
    __syncthreads();

    if (tid < E_) {
        float s = 0.f;
#pragma unroll
        for (int w = 0; w < 32; w++) s = fmaf(s_part[w][tid], s_fac[w], s);
        att_g[b * E_ + tid] = s * s_invL;
    }
}

// ============ gates_k: gates[b][j] for ALL batches, warp per gate row =======
// 128 blocks x 256 threads; block covers gate rows [8*bid, 8*bid+8).
// Weight rows live in registers; 4-batch interleaved dot+reduce.
__global__ __launch_bounds__(256) void gates_kernel(
    const float* __restrict__ att, const float* __restrict__ qt_g,
    const __half* __restrict__ W_ih, const __half* __restrict__ W_hh,
    const float* __restrict__ b_ih, const float* __restrict__ b_hh,
    float* __restrict__ gates)
{
    const int lane = threadIdx.x & 31;
    const int wid  = threadIdx.x >> 5;           // 0..7
    const int j    = blockIdx.x * 8 + wid;       // gate row

    const uint4 wiv = reinterpret_cast<const uint4*>(W_ih + (size_t)j * E_)[lane];
    const uint4 whv = reinterpret_cast<const uint4*>(W_hh + (size_t)j * H_)[lane];
    const __half2* wi2 = reinterpret_cast<const __half2*>(&wiv);
    const __half2* wh2 = reinterpret_cast<const __half2*>(&whv);
    float wi[8], wh[8];
#pragma unroll
    for (int k = 0; k < 4; k++) {
        const float2 a = __half22float2(wi2[k]);
        const float2 c = __half22float2(wh2[k]);
        wi[2 * k] = a.x; wi[2 * k + 1] = a.y;
        wh[2 * k] = c.x; wh[2 * k + 1] = c.y;
    }
    const float bsum = __ldg(&b_ih[j]) + __ldg(&b_hh[j]);

    for (int b0 = 0; b0 < B_; b0 += 4) {
        float d[4];
#pragma unroll
        for (int u = 0; u < 4; u++) {
            const int b = b0 + u;
            const float4 x0 = __ldg(reinterpret_cast<const float4*>(att + b * E_) + lane * 2);
            const float4 x1 = __ldg(reinterpret_cast<const float4*>(att + b * E_) + lane * 2 + 1);
            const float4 q0 = __ldg(reinterpret_cast<const float4*>(qt_g + b * H_) + lane * 2);
            const float4 q1 = __ldg(reinterpret_cast<const float4*>(qt_g + b * H_) + lane * 2 + 1);
            float s = wi[0] * x0.x;
            s = fmaf(wi[1], x0.y, s); s = fmaf(wi[2], x0.z, s); s = fmaf(wi[3], x0.w, s);
            s = fmaf(wi[4], x1.x, s); s = fmaf(wi[5], x1.y, s);
            s = fmaf(wi[6], x1.z, s); s = fmaf(wi[7], x1.w, s);
            s = fmaf(wh[0], q0.x, s); s = fmaf(wh[1], q0.y, s);
            s = fmaf(wh[2], q0.z, s); s = fmaf(wh[3], q0.w, s);
            s = fmaf(wh[4], q1.x, s); s = fmaf(wh[5], q1.y, s);
            s = fmaf(wh[6], q1.z, s); s = fmaf(wh[7], q1.w, s);
            d[u] = s;
        }
#pragma unroll
        for (int o = 16; o; o >>= 1) {
            d[0] += __shfl_xor_sync(0xffffffffu, d[0], o);
            d[1] += __shfl_xor_sync(0xffffffffu, d[1], o);
            d[2] += __shfl_xor_sync(0xffffffffu, d[2], o);
            d[3] += __shfl_xor_sync(0xffffffffu, d[3], o);
        }
        if (lane < 4) gates[(size_t)(b0 + lane) * 4 * H_ + j] = d[lane] + bsum;
    }
}

// ============ out_k: final LSTM update + concat(att, qt) ====================
__global__ __launch_bounds__(512) void out_kernel(
    const float* __restrict__ att, const float* __restrict__ gates,
    const float* __restrict__ ct_g, float* __restrict__ out)
{
    const int b = blockIdx.x;
    const int t = threadIdx.x;   // 512
    if (t < E_) {
        out[b * (E_ + H_) + t] = att[b * E_ + t];
    } else {
        const int h = t - E_;
        float c;
        const float q = lstm_update(gates + b * 4 * H_, h, ct_g[b * H_ + h], &c);
        out[b * (E_ + H_) + t] = q;
    }
}

// ---------------- launch ----------------------------------------------------
extern "C" void kernel_launch(void* const* d_in, const int* in_sizes, int n_in,
                              void* d_out, int out_size)
{
    const float* state = (const float*)d_in[0];
    const int*   length= (const int*)  d_in[1];
    const float* W1    = (const float*)d_in[2];
    const float* b1    = (const float*)d_in[3];
    const float* W2    = (const float*)d_in[4];
    const float* b2    = (const float*)d_in[5];
    const float* W3    = (const float*)d_in[6];
    const float* b3    = (const float*)d_in[7];
    const float* W_ih  = (const float*)d_in[8];
    const float* W_hh  = (const float*)d_in[9];
    const float* b_ih  = (const float*)d_in[10];
    const float* b_hh  = (const float*)d_in[11];
    float* out = (float*)d_out;

    __half *h1, *h2, *w1, *w2, *w3, *wih, *whh, *embh;
    float *att, *qt, *ct, *gates;
    cudaGetSymbolAddress((void**)&h1,    g_h1);
    cudaGetSymbolAddress((void**)&h2,    g_h2);
    cudaGetSymbolAddress((void**)&w1,    g_w1);
    cudaGetSymbolAddress((void**)&w2,    g_w2);
    cudaGetSymbolAddress((void**)&w3,    g_w3);
    cudaGetSymbolAddress((void**)&wih,   g_wih);
    cudaGetSymbolAddress((void**)&whh,   g_whh);
    cudaGetSymbolAddress((void**)&embh,  g_embh);
    cudaGetSymbolAddress((void**)&att,   g_att);
    cudaGetSymbolAddress((void**)&qt,    g_qt);
    cudaGetSymbolAddress((void**)&ct,    g_ct);
    cudaGetSymbolAddress((void**)&gates, g_gates);

    cudaFuncSetAttribute(gemm_f16_kernel<1, 1, 1>,
                         cudaFuncAttributeMaxDynamicSharedMemorySize, GEMM_SM);
    cudaFuncSetAttribute(gemm_f16_kernel<1, 1, 0>,
                         cudaFuncAttributeMaxDynamicSharedMemorySize, GEMM_SM);
    cudaFuncSetAttribute(gemm_f16_kernel<0, 1, 0>,
                         cudaFuncAttributeMaxDynamicSharedMemorySize, GEMM_SM);

    // 1: all weight converts (embedder + LSTM), one launch
    {
        int n = H1_ * D_IN + H2_ * H1_ + E_ * H2_ + 4 * H_ * E_ + 4 * H_ * H_;
        conv_weights_kernel<<<n / 1024, 256>>>(W1, w1, W2, w2, W3, w3,
                                               W_ih, wih, W_hh, whh);
    }

    // 2-4: embedder MLP, single-pass fp16 HMMA (BK=128, warp tile 64x64)
    {
        dim3 g1(H1_ / 256, MROWS / 128);
        gemm_f16_kernel<1, 1, 1><<<g1, 256, GEMM_SM>>>(
            MROWS, H1_, D_IN, nullptr, state, w1, b1, nullptr, h1);
        dim3 g2(H2_ / 256, MROWS / 128);
        gemm_f16_kernel<1, 1, 0><<<g2, 256, GEMM_SM>>>(
            MROWS, H2_, H1_, h1, nullptr, w2, b2, nullptr, h2);
        dim3 g3(E_ / 256, MROWS / 128);
        gemm_f16_kernel<0, 1, 0><<<g3, 256, GEMM_SM>>>(
            MROWS, E_, H2_, h2, nullptr, w3, b3, nullptr, embh);
    }

    // 5..14: shuffle loop: per iteration att_k (update + attention), gates_k
    for (int it = 0; it < NSH; it++) {
        att_kernel<<<B_, 1024>>>(embh, length, gates, qt, ct, att, it == 0);
        gates_kernel<<<B_, 256>>>(att, qt, wih, whh, b_ih, b_hh, gates);
    }

    // 15: final LSTM update + output concat
    out_kernel<<<B_, 512>>>(att, gates, ct, out);
}

// round 15
// speedup vs baseline: 1.9430x; 1.9430x over previous
#include <cuda_runtime.h>
#include <cuda_fp16.h>
#include <math.h>
#include <stdint.h>

// Problem constants
#define B_    128
#define F_    1024
#define D_IN  128
#define H1_   512
#define H2_   512
#define E_    256
#define H_    256
#define NSH   5
#define MROWS (B_ * F_)   // 131072

// ---------------- scratch (device globals; no allocation allowed) ----------
__device__ __half g_h1[(size_t)MROWS * H1_];
__device__ __half g_h2[(size_t)MROWS * H2_];
__device__ __half g_w1[H1_ * D_IN];
__device__ __half g_w2[H2_ * H1_];
__device__ __half g_w3[E_ * H2_];
__device__ __half g_wih[4 * H_ * E_];
__device__ __half g_whh[4 * H_ * H_];
__device__ __half g_embh[(size_t)MROWS * E_];   // compacted fp16 emb
__device__ int    g_off[B_ + 1];
__device__ int    g_totp[1];
__device__ int    g_rowmap[MROWS];

// ===================== low-level helpers ===================================
__device__ __forceinline__ uint32_t smem_u32(const void* p) {
    uint32_t a;
    asm("{ .reg .u64 t; cvta.to.shared.u64 t, %1; cvt.u32.u64 %0, t; }"
        : "=r"(a) : "l"(p));
    return a;
}

__device__ __forceinline__ void cp_async16(uint32_t dst, const void* src) {
    asm volatile("cp.async.cg.shared.global [%0], [%1], 16;\n"
                 :: "r"(dst), "l"(src));
}
#define CP_COMMIT() asm volatile("cp.async.commit_group;\n" ::: "memory")
#define CP_WAIT1()  asm volatile("cp.async.wait_group 1;\n" ::: "memory")
#define CP_WAIT0()  asm volatile("cp.async.wait_group 0;\n" ::: "memory")

__device__ __forceinline__ void ldsm4(uint32_t* r, uint32_t addr) {
    asm volatile("ldmatrix.sync.aligned.m8n8.x4.shared.b16 {%0,%1,%2,%3}, [%4];\n"
                 : "=r"(r[0]), "=r"(r[1]), "=r"(r[2]), "=r"(r[3]) : "r"(addr));
}

// fp16 HMMA m16n8k16, fp32 accumulate
__device__ __forceinline__ void mma_f16(float* d, const uint32_t* a, const uint32_t* b) {
    asm volatile(
        "mma.sync.aligned.m16n8k16.row.col.f32.f16.f16.f32 "
        "{%0,%1,%2,%3}, {%4,%5,%6,%7}, {%8,%9}, {%0,%1,%2,%3};\n"
        : "+f"(d[0]), "+f"(d[1]), "+f"(d[2]), "+f"(d[3])
        : "r"(a[0]), "r"(a[1]), "r"(a[2]), "r"(a[3]), "r"(b[0]), "r"(b[1]));
}

__device__ __forceinline__ uint32_t pack_h2(float a, float b) {
    __half2 t = __floats2half2_rn(a, b);
    return reinterpret_cast<uint32_t&>(t);
}

// ============ scan + rowmap: compact valid (b,f) rows ======================
__global__ __launch_bounds__(B_) void scan_kernel(
    const int* __restrict__ length, int* __restrict__ off, int* __restrict__ totp)
{
    __shared__ int s[B_];
    const int t = threadIdx.x;
    const int len = length[t];
    s[t] = len;
    __syncthreads();
    for (int d = 1; d < B_; d <<= 1) {
        const int v = (t >= d) ? s[t - d] : 0;
        __syncthreads();
        s[t] += v;
        __syncthreads();
    }
    off[t] = s[t] - len;           // exclusive prefix
    if (t == B_ - 1) {
        off[B_] = s[t];
        totp[0] = (s[t] + 127) & ~127;
    }
}

__global__ __launch_bounds__(256) void rowmap_kernel(
    const int* __restrict__ length, const int* __restrict__ off,
    const int* __restrict__ totp, int* __restrict__ rowmap)
{
    const int b = blockIdx.x;
    const int base = off[b];
    const int len = length[b];
    for (int i = threadIdx.x; i < len; i += 256)
        rowmap[base + i] = b * F_ + i;
    if (b == B_ - 1) {
        const int tot = off[B_];
        const int tp  = totp[0];
        for (int i = tot + threadIdx.x; i < tp; i += 256)
            rowmap[i] = 0;
    }
}

// =================== fp16 HMMA GEMM: C = act(A @ W^T + bias) ================
// CTA tile 128x256, 256 threads, warp grid 2m x 4n, warp tile 64x64.
// BK=128 (256B rows, XOR swizzle), 2-stage cp.async, 1 CTA/SM.
// CONV_A: A fp32 in global, gathered through rowmap (layer 1 only).
// All grids launched worst-case; blocks with m0 >= *totp exit immediately.
static constexpr int TA      = 128 * 256;          // 32768 B  A tile
static constexpr int TW      = 256 * 256;          // 65536 B  W tile
static constexpr int OFF_A   = 0;
static constexpr int OFF_W   = TA;
static constexpr int STAGE_B = TA + TW;            // 98304 B
static constexpr int GEMM_SM = 2 * STAGE_B;        // 196608 B

template <int ACT, int OUT_HALF, int CONV_A>
__global__ __launch_bounds__(256, 1) void gemm_f16_kernel(
    int M, int N, int K,
    const __half* __restrict__ A, const float* __restrict__ Afp,
    const __half* __restrict__ W,
    const float* __restrict__ bias,
    float* __restrict__ C, __half* __restrict__ Ch,
    const int* __restrict__ rowmap, const int* __restrict__ totp)
{
    const int m0 = blockIdx.y * 128;
    if (m0 >= *totp) return;   // compacted-row early exit (uniform per block)

    extern __shared__ char smem[];
    const uint32_t sbase = smem_u32(smem);
    const int tid  = threadIdx.x;
    const int lane = tid & 31;
    const int wid  = tid >> 5;            // 0..7
    const int n0 = blockIdx.x * 256;
    const int wm = (wid & 1) * 64;        // warp m-offset
    const int wn = (wid >> 1) * 64;       // warp n-offset (0..192)

    float acc[4][8][4];
#pragma unroll
    for (int i = 0; i < 4; i++)
#pragma unroll
        for (int j = 0; j < 8; j++)
#pragma unroll
            for (int k = 0; k < 4; k++) acc[i][j][k] = 0.f;

    // ---- ldmatrix row bases ----
    uint32_t aRow[4], aX[4];
#pragma unroll
    for (int am = 0; am < 4; am++) {
        const int r = wm + am * 16 + (lane & 15);
        aRow[am] = (uint32_t)(r * 256);
        aX[am]   = (uint32_t)(r & 7);
    }
    uint32_t bRow[4], bX[4];
#pragma unroll
    for (int pb = 0; pb < 4; pb++) {
        const int r = wn + pb * 16 + (lane & 7) + ((lane >> 1) & 8);
        bRow[pb] = (uint32_t)(r * 256);
        bX[pb]   = (uint32_t)(r & 7);
    }
    const uint32_t ac0 = (uint32_t)(lane >> 4);
    const uint32_t bc0 = (uint32_t)((lane >> 3) & 1);

    const int NC = K >> 7;   // chunks of 128 fp16

    auto prefetch = [&](int cc, int st) {
        const uint32_t so = sbase + (uint32_t)(st * STAGE_B);
        const int kk = cc * 128;
#pragma unroll
        for (int i = 0; i < 16; i++) {
            const int id  = i * 256 + tid;       // 0..4095
            const int row = id >> 4;
            const int c16 = id & 15;
            cp_async16(so + OFF_W + row * 256 + (((uint32_t)(c16 ^ (row & 7))) << 4),
                       W + (size_t)(n0 + row) * K + kk + c16 * 8);
        }
        if (CONV_A) {
#pragma unroll
            for (int i = 0; i < 8; i++) {
                const int id  = i * 256 + tid;   // 0..2047
                const int row = id >> 4;
                const int c16 = id & 15;
                const int grow = rowmap[m0 + row];   // gather
                const float* src = Afp + (size_t)grow * K + kk + c16 * 8;
                const float4 u = *reinterpret_cast<const float4*>(src);
                const float4 v = *reinterpret_cast<const float4*>(src + 4);
                uint4 pk;
                pk.x = pack_h2(u.x, u.y); pk.y = pack_h2(u.z, u.w);
                pk.z = pack_h2(v.x, v.y); pk.w = pack_h2(v.z, v.w);
                *reinterpret_cast<uint4*>(
                    smem + (so - sbase) + OFF_A + row * 256
                    + (((uint32_t)(c16 ^ (row & 7))) << 4)) = pk;
            }
        } else {
#pragma unroll
            for (int i = 0; i < 8; i++) {
                const int id  = i * 256 + tid;
                const int row = id >> 4;
                const int c16 = id & 15;
                cp_async16(so + OFF_A + row * 256 + (((uint32_t)(c16 ^ (row & 7))) << 4),
                           A + (size_t)(m0 + row) * K + kk + c16 * 8);
            }
        }
        CP_COMMIT();
    };

    prefetch(0, 0);

    for (int cc = 0; cc < NC; cc++) {
        if (cc + 1 < NC) { prefetch(cc + 1, (cc + 1) & 1); CP_WAIT1(); }
        else             { CP_WAIT0(); }
        __syncthreads();

        const uint32_t st = sbase + (cc & 1) * STAGE_B;
#pragma unroll
        for (int s = 0; s < 8; s++) {
            const uint32_t ac = ac0 + 2 * s;
            const uint32_t bc = bc0 + 2 * s;

            uint32_t ah[4][4];
#pragma unroll
            for (int am = 0; am < 4; am++)
                ldsm4(ah[am], st + OFF_A + aRow[am] + ((ac ^ aX[am]) << 4));
            uint32_t bv[8][2];
#pragma unroll
            for (int pb = 0; pb < 4; pb++) {
                uint32_t r[4];
                ldsm4(r, st + OFF_W + bRow[pb] + ((bc ^ bX[pb]) << 4));
                bv[2 * pb][0] = r[0]; bv[2 * pb][1] = r[1];
                bv[2 * pb + 1][0] = r[2]; bv[2 * pb + 1][1] = r[3];
            }
#pragma unroll
            for (int am = 0; am < 4; am++)
#pragma unroll
                for (int an = 0; an < 8; an++) mma_f16(acc[am][an], ah[am], bv[an]);
        }
        __syncthreads();
    }

    // epilogue: bias (+ReLU), store fp32 or fp16 (compacted rows)
#pragma unroll
    for (int am = 0; am < 4; am++) {
        const int r0 = m0 + wm + am * 16 + (lane >> 2);
        const int r1 = r0 + 8;
#pragma unroll
        for (int an = 0; an < 8; an++) {
            const int col = n0 + wn + an * 8 + ((lane & 3) << 1);
            const float bz0 = __ldg(&bias[col]);
            const float bz1 = __ldg(&bias[col + 1]);
            float v00 = acc[am][an][0] + bz0;
            float v01 = acc[am][an][1] + bz1;
            float v10 = acc[am][an][2] + bz0;
            float v11 = acc[am][an][3] + bz1;
            if (ACT) {
                v00 = fmaxf(v00, 0.f); v01 = fmaxf(v01, 0.f);
                v10 = fmaxf(v10, 0.f); v11 = fmaxf(v11, 0.f);
            }
            if (OUT_HALF) {
                *reinterpret_cast<uint32_t*>(&Ch[(size_t)r0 * N + col]) = pack_h2(v00, v01);
                *reinterpret_cast<uint32_t*>(&Ch[(size_t)r1 * N + col]) = pack_h2(v10, v11);
            } else {
                *reinterpret_cast<float2*>(&C[(size_t)r0 * N + col]) = make_float2(v00, v01);
                *reinterpret_cast<float2*>(&C[(size_t)r1 * N + col]) = make_float2(v10, v11);
            }
        }
    }
}

// ---------------- fp32 -> fp16 converts (all weights, one launch) ----------
__device__ __forceinline__ void conv4(const float* src, __half* dst, int i) {
    float4 v = *reinterpret_cast<const float4*>(src + i);
    *reinterpret_cast<uint2*>(&dst[i]) =
        make_uint2(pack_h2(v.x, v.y), pack_h2(v.z, v.w));
}

__global__ __launch_bounds__(256) void conv_weights_kernel(
    const float* __restrict__ W1, __half* __restrict__ w1,
    const float* __restrict__ W2, __half* __restrict__ w2,
    const float* __restrict__ W3, __half* __restrict__ w3,
    const float* __restrict__ Wih, __half* __restrict__ wih,
    const float* __restrict__ Whh, __half* __restrict__ whh)
{
    const int N1 = H1_ * D_IN, N2 = H2_ * H1_, N3 = E_ * H2_;
    const int N4 = 4 * H_ * E_, N5 = 4 * H_ * H_;
    int i = (blockIdx.x * 256 + threadIdx.x) * 4;
    if (i < N1)                      conv4(W1, w1, i);
    else if (i < N1 + N2)            conv4(W2, w2, i - N1);
    else if (i < N1 + N2 + N3)       conv4(W3, w3, i - N1 - N2);
    else if (i < N1 + N2 + N3 + N4)  conv4(Wih, wih, i - N1 - N2 - N3);
    else if (i < N1 + N2 + N3 + N4 + N5) conv4(Whh, whh, i - N1 - N2 - N3 - N4);
}

// ============ fused shuffle: 5 x (online-softmax attention + LSTM) =========
// One block per batch, 1024 threads. emb compacted fp16: batch b's rows are
// [off[b], off[b]+len). Warp w streams f = w, w+32, ... < len (no masking).
__global__ __launch_bounds__(1024) void shuffle_kernel(
    const __half* __restrict__ emb, const int* __restrict__ length,
    const int* __restrict__ off,
    const __half* __restrict__ W_ih, const __half* __restrict__ W_hh,
    const float* __restrict__ b_ih, const float* __restrict__ b_hh,
    float* __restrict__ out)
{
    const int b    = blockIdx.x;
    const int tid  = threadIdx.x;
    const int warp = tid >> 5, lane = tid & 31;

    __shared__ __align__(16) float s_q[H_];
    __shared__ __align__(16) float s_c[H_];
    __shared__ __align__(16) float s_x[E_];
    __shared__ __align__(16) float s_g[4 * H_];
    __shared__ __align__(16) float s_part[32][E_ + 4];
    __shared__ float s_m[32], s_l[32], s_fac[32];
    __shared__ float s_invL;

    if (tid < H_) { s_q[tid] = 0.f; s_c[tid] = 0.f; }
    __syncthreads();

    const int len = length[b];
    const __half* eb = emb + (size_t)off[b] * E_;
    const float4* q4 = reinterpret_cast<const float4*>(s_q);
    const float4* x4 = reinterpret_cast<const float4*>(s_x);

    for (int it = 0; it < NSH; it++) {
        // ---- single-pass attention over valid rows only ----
        float m = -INFINITY, l = 0.f;
        float acc[8];
#pragma unroll
        for (int j = 0; j < 8; j++) acc[j] = 0.f;
        const float4 qa = q4[lane * 2], qb = q4[lane * 2 + 1];
        const float qv[8] = { qa.x, qa.y, qa.z, qa.w, qb.x, qb.y, qb.z, qb.w };
        for (int f = warp; f < len; f += 32) {
            const uint4 hv = reinterpret_cast<const uint4*>(eb + (size_t)f * E_)[lane];
            const __half2* hp = reinterpret_cast<const __half2*>(&hv);
            float v[8];
#pragma unroll
            for (int k = 0; k < 4; k++) {
                const float2 f2 = __half22float2(hp[k]);
                v[2 * k] = f2.x; v[2 * k + 1] = f2.y;
            }
            float d = v[0] * qv[0];
#pragma unroll
            for (int j = 1; j < 8; j++) d = fmaf(v[j], qv[j], d);
#pragma unroll
            for (int o = 16; o; o >>= 1) d += __shfl_xor_sync(0xffffffffu, d, o);
            const float mn = fmaxf(m, d);
            const float sc = expf(m - mn);
            const float p  = expf(d - mn);
            l = l * sc + p;
#pragma unroll
            for (int j = 0; j < 8; j++) acc[j] = fmaf(acc[j], sc, p * v[j]);
            m = mn;
        }
        {
            float4* sp = reinterpret_cast<float4*>(s_part[warp]);
            sp[lane * 2]     = make_float4(acc[0], acc[1], acc[2], acc[3]);
            sp[lane * 2 + 1] = make_float4(acc[4], acc[5], acc[6], acc[7]);
            if (lane == 0) { s_m[warp] = m; s_l[warp] = l; }
        }
        __syncthreads();

        // ---- combine 32 warp-partials (warp 0) ----
        if (tid < 32) {
            const float mw = s_m[tid];
            float M = mw;
#pragma unroll
            for (int o = 16; o; o >>= 1) M = fmaxf(M, __shfl_xor_sync(0xffffffffu, M, o));
            const float fac = (mw == -INFINITY) ? 0.f : expf(mw - M);
            s_fac[tid] = fac;
            float L = s_l[tid] * fac;
#pragma unroll
            for (int o = 16; o; o >>= 1) L += __shfl_xor_sync(0xffffffffu, L, o);
            if (tid == 0) s_invL = 1.f / L;
        }
        __syncthreads();

        if (tid < E_) {
            float s = 0.f;
#pragma unroll
            for (int w = 0; w < 32; w++) s = fmaf(s_part[w][tid], s_fac[w], s);
            s_x[tid] = s * s_invL;
        }
        __syncthreads();

        // ---- LSTM gates: warp per 32 rows, fp16 weights ----
        {
            const float4 xa = x4[lane * 2], xb = x4[lane * 2 + 1];
            const float xv[8] = { xa.x, xa.y, xa.z, xa.w, xb.x, xb.y, xb.z, xb.w };
            const float4 qa2 = q4[lane * 2], qb2 = q4[lane * 2 + 1];
            const float qw[8] = { qa2.x, qa2.y, qa2.z, qa2.w, qb2.x, qb2.y, qb2.z, qb2.w };
            for (int j = warp * 32, je = j + 32; j < je; j++) {
                const uint4 wiv = reinterpret_cast<const uint4*>(W_ih + (size_t)j * E_)[lane];
                const uint4 whv = reinterpret_cast<const uint4*>(W_hh + (size_t)j * H_)[lane];
                const __half2* wi2 = reinterpret_cast<const __half2*>(&wiv);
                const __half2* wh2 = reinterpret_cast<const __half2*>(&whv);
                float d = 0.f;
#pragma unroll
                for (int k = 0; k < 4; k++) {
                    const float2 wi = __half22float2(wi2[k]);
                    const float2 wh = __half22float2(wh2[k]);
                    d = fmaf(wi.x, xv[2 * k], d);
                    d = fmaf(wi.y, xv[2 * k + 1], d);
                    d = fmaf(wh.x, qw[2 * k], d);
                    d = fmaf(wh.y, qw[2 * k + 1], d);
                }
#pragma unroll
                for (int o = 16; o; o >>= 1) d += __shfl_xor_sync(0xffffffffu, d, o);
                if (lane == 0) s_g[j] = d + b_ih[j] + b_hh[j];
            }
        }
        __syncthreads();

        // ---- state update (gate order i, f, g, o) ----
        if (tid < H_) {
            const float gi = 1.f / (1.f + expf(-s_g[tid]));
            const float gf = 1.f / (1.f + expf(-s_g[H_ + tid]));
            const float gg = tanhf(s_g[2 * H_ + tid]);
            const float go = 1.f / (1.f + expf(-s_g[3 * H_ + tid]));
            const float c = gf * s_c[tid] + gi * gg;
            s_c[tid] = c;
            s_q[tid] = go * tanhf(c);
        }
        __syncthreads();
    }

    // ---- output: concat(attended, qt) ----
    if (tid < E_ + H_)
        out[b * (E_ + H_) + tid] = (tid < E_) ? s_x[tid] : s_q[tid - E_];
}

// ---------------- launch ----------------------------------------------------
extern "C" void kernel_launch(void* const* d_in, const int* in_sizes, int n_in,
                              void* d_out, int out_size)
{
    const float* state = (const float*)d_in[0];
    const int*   length= (const int*)  d_in[1];
    const float* W1    = (const float*)d_in[2];
    const float* b1    = (const float*)d_in[3];
    const float* W2    = (const float*)d_in[4];
    const float* b2    = (const float*)d_in[5];
    const float* W3    = (const float*)d_in[6];
    const float* b3    = (const float*)d_in[7];
    const float* W_ih  = (const float*)d_in[8];
    const float* W_hh  = (const float*)d_in[9];
    const float* b_ih  = (const float*)d_in[10];
    const float* b_hh  = (const float*)d_in[11];
    float* out = (float*)d_out;

    __half *h1, *h2, *w1, *w2, *w3, *wih, *whh, *embh;
    int *off, *totp, *rowmap;
    cudaGetSymbolAddress((void**)&h1,     g_h1);
    cudaGetSymbolAddress((void**)&h2,     g_h2);
    cudaGetSymbolAddress((void**)&w1,     g_w1);
    cudaGetSymbolAddress((void**)&w2,     g_w2);
    cudaGetSymbolAddress((void**)&w3,     g_w3);
    cudaGetSymbolAddress((void**)&wih,    g_wih);
    cudaGetSymbolAddress((void**)&whh,    g_whh);
    cudaGetSymbolAddress((void**)&embh,   g_embh);
    cudaGetSymbolAddress((void**)&off,    g_off);
    cudaGetSymbolAddress((void**)&totp,   g_totp);
    cudaGetSymbolAddress((void**)&rowmap, g_rowmap);

    cudaFuncSetAttribute(gemm_f16_kernel<1, 1, 1>,
                         cudaFuncAttributeMaxDynamicSharedMemorySize, GEMM_SM);
    cudaFuncSetAttribute(gemm_f16_kernel<1, 1, 0>,
                         cudaFuncAttributeMaxDynamicSharedMemorySize, GEMM_SM);
    cudaFuncSetAttribute(gemm_f16_kernel<0, 1, 0>,
                         cudaFuncAttributeMaxDynamicSharedMemorySize, GEMM_SM);

    // 1: all weight converts
    {
        int n = H1_ * D_IN + H2_ * H1_ + E_ * H2_ + 4 * H_ * E_ + 4 * H_ * H_;
        conv_weights_kernel<<<n / 1024, 256>>>(W1, w1, W2, w2, W3, w3,
                                               W_ih, wih, W_hh, whh);
    }
    // 2-3: compaction metadata
    scan_kernel<<<1, B_>>>(length, off, totp);
    rowmap_kernel<<<B_, 256>>>(length, off, totp, rowmap);

    // 4-6: embedder MLP on compacted rows (worst-case grid + early exit)
    {
        dim3 g1(H1_ / 256, MROWS / 128);
        gemm_f16_kernel<1, 1, 1><<<g1, 256, GEMM_SM>>>(
            MROWS, H1_, D_IN, nullptr, state, w1, b1, nullptr, h1, rowmap, totp);
        dim3 g2(H2_ / 256, MROWS / 128);
        gemm_f16_kernel<1, 1, 0><<<g2, 256, GEMM_SM>>>(
            MROWS, H2_, H1_, h1, nullptr, w2, b2, nullptr, h2, rowmap, totp);
        dim3 g3(E_ / 256, MROWS / 128);
        gemm_f16_kernel<0, 1, 0><<<g3, 256, GEMM_SM>>>(
            MROWS, E_, H2_, h2, nullptr, w3, b3, nullptr, embh, rowmap, totp);
    }

    // 7: fused shuffle loop on compacted emb
    shuffle_kernel<<<B_, 1024>>>(embh, length, off, wih, whh, b_ih, b_hh, out);
}